// round 14
// baseline (speedup 1.0000x reference)
#include <cuda_runtime.h>
#include <math.h>

#define BT    3840
#define NROWS 76800

__device__ float g_tok [BT*19*32];
__device__ float g_tok2[NROWS*32];
__device__ float g_hm  [BT*32];
__device__ float g_hcat[BT*32];
__device__ float g_xg  [64*120*64];

__constant__ unsigned c_maskb[20] = {
    0x1Fu,0x73u,0x1DDu,0x33Du,0x23Bu,0x67Au,0xC76u,0x3984u,0x779Cu,0xE738u,
    0x1CF70u,0x18CC0u,0x33180u,0x2F380u,0x6E700u,0x5EE00u,0x59C00u,0x67000u,0x7C000u,0xFFFFFu
};

typedef unsigned long long ull;

__device__ __forceinline__ ull pack2(float lo, float hi){
    ull r;
    asm("mov.b64 %0, {%1, %2};" : "=l"(r) : "f"(lo), "f"(hi));
    return r;
}
__device__ __forceinline__ void unpack2(ull v, float& lo, float& hi){
    asm("mov.b64 {%0, %1}, %2;" : "=f"(lo), "=f"(hi) : "l"(v));
}
__device__ __forceinline__ void ffma2(ull& d, ull a, ull b){
    asm("fma.rn.f32x2 %0, %1, %2, %0;" : "+l"(d) : "l"(a), "l"(b));
}
__device__ __forceinline__ float fsig(float x){ return __fdividef(1.f, 1.f + __expf(-x)); }
__device__ __forceinline__ float ftanh(float x){
    float ax = fabsf(x);
    float e  = __expf(2.f*ax);
    float t  = 1.f - __fdividef(2.f, e + 1.f);
    return (x < 0.f) ? -t : t;
}

// ---------------- CNN: warp = sample pair; conv2 via packed f32x2 FMA
// 512 threads (16 warps, 32 samples) per block -> 2 blocks/SM = 32 warps/SM.
__global__ __launch_bounds__(512, 2) void k_cnn(
    const float* __restrict__ x, const float* __restrict__ c1w, const float* __restrict__ c1b,
    const float* __restrict__ c2w, const float* __restrict__ c2b, const float* __restrict__ pos)
{
    extern __shared__ __align__(16) float sm[];
    float* w2s = sm;              // 5120
    float* b2s = sm + 5120;       // 32
    float* uni = sm + 5152;       // union: sx[6400] then h1p[16*1408=22528]
    float* sx  = uni;
    float* h1p = uni;

    int tid = threadIdx.x, w = tid >> 5, oc = tid & 31;
    int n0 = blockIdx.x * 32;

    for (int i = tid; i < 5120; i += 512) {
        int o = i/160, r = i - o*160, ic = r/5, k = r - ic*5;
        w2s[(ic*5+k)*32 + o] = c2w[i];
    }
    if (tid < 32) b2s[tid] = c2b[tid];
    {
        const float4* xg = (const float4*)(x + (size_t)n0*200);
        float4* sx4 = (float4*)sx;
        for (int i = tid; i < 1600; i += 512) sx4[i] = xg[i];
    }
    __syncthreads();

    float w1r[5];
    #pragma unroll
    for (int k = 0; k < 5; k++) w1r[k] = c1w[oc*5+k];
    float b1 = c1b[oc];
    float po[2][20];
    #pragma unroll
    for (int s = 0; s < 2; s++) {
        const float* xs = sx + (2*w+s)*200;
        #pragma unroll 4
        for (int j = 0; j < 20; j++) {
            const float2* xw = (const float2*)(xs + 10*j);
            float2 f0 = xw[0], f1 = xw[1], f2 = xw[2], f3 = xw[3], f4 = xw[4];
            float o0 = b1, o1 = b1;
            o0 += f0.x*w1r[0]; o0 += f0.y*w1r[1]; o0 += f1.x*w1r[2];
            o0 += f1.y*w1r[3]; o0 += f2.x*w1r[4];
            o1 += f2.y*w1r[0]; o1 += f3.x*w1r[1]; o1 += f3.y*w1r[2];
            o1 += f4.x*w1r[3]; o1 += f4.y*w1r[4];
            po[s][j] = fmaxf(fmaxf(o0,0.f), fmaxf(o1,0.f));
        }
    }
    __syncthreads();

    float* hw = h1p + w*1408;
    #pragma unroll
    for (int t = 0; t < 20; t += 2) {
        float4 v = make_float4(po[0][t], po[1][t], po[0][t+1], po[1][t+1]);
        *(float4*)(hw + oc*44 + t*2) = v;
    }
    __syncwarp();

    ull acc[8];
    #pragma unroll
    for (int j = 0; j < 8; j++) acc[j] = 0ULL;
    #pragma unroll 2
    for (int ic = 0; ic < 32; ic++) {
        const ulonglong2* pv = (const ulonglong2*)(hw + ic*44);
        ull pr[20];
        #pragma unroll
        for (int q = 0; q < 10; q++) { ulonglong2 u = pv[q]; pr[2*q] = u.x; pr[2*q+1] = u.y; }
        ull wp[5];
        #pragma unroll
        for (int k = 0; k < 5; k++) { float wv_ = w2s[(ic*5+k)*32+oc]; wp[k] = pack2(wv_, wv_); }
        #pragma unroll
        for (int j = 0; j < 8; j++) {
            #pragma unroll
            for (int k = 0; k < 5; k++) ffma2(acc[j], pr[2*j+k], wp[k]);
        }
    }
    float aA[8], aB[8];
    #pragma unroll
    for (int j = 0; j < 8; j++) unpack2(acc[j], aA[j], aB[j]);
    float b2r = b2s[oc];
    #pragma unroll
    for (int s = 0; s < 2; s++) {
        const float* a = s ? aB : aA;
        float v = 0.f;
        #pragma unroll
        for (int u = 0; u < 4; u++)
            v += fmaxf(fmaxf(a[2*u]+b2r, 0.f), fmaxf(a[2*u+1]+b2r, 0.f));
        int n = n0 + 2*w + s, c = n % 19;
        g_tok[(size_t)n*32 + oc] = 0.25f*v + pos[c*32+oc];
    }
}

// ---------------- fused QKV + attention + proj + LN1 ; 4 samples/block, 320 thr, 3 blk/SM
__global__ __launch_bounds__(320, 3) void k_xform(
    const float* __restrict__ wq, const float* __restrict__ bq,
    const float* __restrict__ wk, const float* __restrict__ bk,
    const float* __restrict__ wv, const float* __restrict__ bv,
    const float* __restrict__ wo, const float* __restrict__ bo,
    const float* __restrict__ g1, const float* __restrict__ be1,
    const float* __restrict__ pos)
{
    extern __shared__ __align__(16) float smx[];
    float* WT   = smx;            // 3072
    float* sbq  = smx + 3072;     // 96
    float* WOT  = smx + 3168;     // 1024
    float* sbo  = smx + 4192;     // 32
    float* sg   = smx + 4224;     // 32
    float* sbe  = smx + 4256;     // 32
    float* As   = smx + 4288;     // 80*33
    float* QKV  = smx + 6928;     // 4*2160
    float* Os   = smx + 15568;    // 80*36
    float* smu  = smx + 18448;    // 80
    float* srs  = smx + 18528;    // 80

    int tid = threadIdx.x;
    int s0 = blockIdx.x * 4;

    for (int i = tid; i < 3072; i += 320) {
        int j = i/96, n = i%96;
        WT[i] = (n<32) ? wq[n*32+j] : (n<64) ? wk[(n-32)*32+j] : wv[(n-64)*32+j];
    }
    for (int i = tid; i < 96; i += 320) sbq[i] = (i<32)?bq[i]:(i<64)?bk[i-32]:bv[i-64];
    for (int i = tid; i < 1024; i += 320) { int d = i>>5, j = i&31; WOT[j*32+d] = wo[i]; }
    if (tid < 32) { sbo[tid]=bo[tid]; sg[tid]=g1[tid]; sbe[tid]=be1[tid]; }
    for (int i = tid; i < 640; i += 320) {
        int rr = i>>3, d4 = (i&7)*4;
        int sl = rr/20, t = rr - sl*20;
        const float4 v = (t < 19)
            ? *(const float4*)(g_tok + ((size_t)(s0+sl)*19 + t)*32 + d4)
            : *(const float4*)(pos + 19*32 + d4);
        float* d = As + rr*33 + d4;
        d[0]=v.x; d[1]=v.y; d[2]=v.z; d[3]=v.w;
    }
    __syncthreads();

    {
        int rowg = tid>>3, colg = tid&7;
        ull ap0[6], ap1[6];
        #pragma unroll
        for (int c = 0; c < 6; c++) { ap0[c]=0ULL; ap1[c]=0ULL; }
        #pragma unroll 8
        for (int j = 0; j < 32; j++) {
            float a0 = As[(2*rowg)*33+j], a1 = As[(2*rowg+1)*33+j];
            ull a0p = pack2(a0,a0), a1p = pack2(a1,a1);
            const ulonglong2* wp2 = (const ulonglong2*)(WT + j*96 + colg*12);
            ulonglong2 wA = wp2[0], wB = wp2[1], wC = wp2[2];
            ffma2(ap0[0], wA.x, a0p); ffma2(ap0[1], wA.y, a0p);
            ffma2(ap0[2], wB.x, a0p); ffma2(ap0[3], wB.y, a0p);
            ffma2(ap0[4], wC.x, a0p); ffma2(ap0[5], wC.y, a0p);
            ffma2(ap1[0], wA.x, a1p); ffma2(ap1[1], wA.y, a1p);
            ffma2(ap1[2], wB.x, a1p); ffma2(ap1[3], wB.y, a1p);
            ffma2(ap1[4], wC.x, a1p); ffma2(ap1[5], wC.y, a1p);
        }
        float acc0[12], acc1[12];
        #pragma unroll
        for (int c = 0; c < 6; c++) {
            unpack2(ap0[c], acc0[2*c], acc0[2*c+1]);
            unpack2(ap1[c], acc1[2*c], acc1[2*c+1]);
        }
        #pragma unroll
        for (int c = 0; c < 12; c++) {
            int n = colg*12 + c;
            int which = n>>5, d = n&31;
            float b = sbq[n];
            int rr0 = 2*rowg, rr1 = rr0+1;
            int sl0 = rr0/20, t0 = rr0 - sl0*20;
            int sl1 = rr1/20, t1 = rr1 - sl1*20;
            QKV[sl0*2160 + which*720 + t0*36 + d] = acc0[c] + b;
            QKV[sl1*2160 + which*720 + t1*36 + d] = acc1[c] + b;
        }
    }
    __syncthreads();

    #pragma unroll
    for (int pass = 0; pass < 2; pass++) {
        int hi = (tid >= 160);
        int sl = pass*2 + hi;
        int slot = tid - hi*160;
        int t = slot>>3, h = slot&7;
        const float* qs = QKV + sl*2160;
        const float* ks = qs + 720;
        const float* vs = qs + 1440;
        float4 q4 = *(const float4*)(qs + t*36 + h*4);
        unsigned mb = c_maskb[t];
        float sc[20], mx = -1e30f;
        #pragma unroll
        for (int kt = 0; kt < 20; kt++) {
            float4 k4 = *(const float4*)(ks + kt*36 + h*4);
            float s = 0.5f*(q4.x*k4.x+q4.y*k4.y+q4.z*k4.z+q4.w*k4.w);
            if (!((mb>>kt)&1u)) s = -1e9f;
            sc[kt] = s; mx = fmaxf(mx, s);
        }
        float sum = 0.f;
        #pragma unroll
        for (int kt = 0; kt < 20; kt++) { sc[kt] = __expf(sc[kt]-mx); sum += sc[kt]; }
        float inv = __fdividef(1.f, sum);
        float4 o = make_float4(0.f,0.f,0.f,0.f);
        #pragma unroll
        for (int kt = 0; kt < 20; kt++) {
            float a = sc[kt];
            float4 v4 = *(const float4*)(vs + kt*36 + h*4);
            o.x += a*v4.x; o.y += a*v4.y; o.z += a*v4.z; o.w += a*v4.w;
        }
        o.x *= inv; o.y *= inv; o.z *= inv; o.w *= inv;
        *(float4*)(Os + (sl*20 + t)*36 + h*4) = o;
    }
    __syncthreads();

    float* Ps = QKV;
    {
        int rowg = tid>>3, colg = tid&7;
        ull p0[2], p1[2];
        p0[0]=p0[1]=p1[0]=p1[1]=0ULL;
        #pragma unroll 8
        for (int j = 0; j < 32; j++) {
            const ulonglong2 wv2 = *(const ulonglong2*)(WOT + j*32 + colg*4);
            float x0 = Os[(2*rowg)*36+j], x1 = Os[(2*rowg+1)*36+j];
            ull x0p = pack2(x0,x0), x1p = pack2(x1,x1);
            ffma2(p0[0], wv2.x, x0p); ffma2(p0[1], wv2.y, x0p);
            ffma2(p1[0], wv2.x, x1p); ffma2(p1[1], wv2.y, x1p);
        }
        float a0[4], a1[4];
        unpack2(p0[0], a0[0], a0[1]); unpack2(p0[1], a0[2], a0[3]);
        unpack2(p1[0], a1[0], a1[1]); unpack2(p1[1], a1[2], a1[3]);
        #pragma unroll
        for (int i = 0; i < 2; i++) {
            int rr = 2*rowg + i;
            const float* res = As + rr*33 + colg*4;
            const float* ac = i ? a1 : a0;
            float* d = Ps + rr*33 + colg*4;
            d[0]=ac[0]+sbo[colg*4+0]+res[0];
            d[1]=ac[1]+sbo[colg*4+1]+res[1];
            d[2]=ac[2]+sbo[colg*4+2]+res[2];
            d[3]=ac[3]+sbo[colg*4+3]+res[3];
        }
    }
    __syncthreads();
    if (tid < 80) {
        const float* row = Ps + tid*33;
        float mu = 0.f;
        #pragma unroll
        for (int j = 0; j < 32; j++) mu += row[j];
        mu *= 0.03125f;
        float var = 0.f;
        #pragma unroll
        for (int j = 0; j < 32; j++) { float dd = row[j]-mu; var += dd*dd; }
        smu[tid] = mu; srs[tid] = rsqrtf(var*0.03125f + 1e-5f);
    }
    __syncthreads();
    size_t base = (size_t)blockIdx.x * 80 * 32;
    for (int i = tid; i < 2560; i += 320) {
        int rr = i>>5, d = i&31;
        g_tok2[base + i] = (Ps[rr*33+d]-smu[rr])*srs[rr]*sg[d] + sbe[d];
    }
}

// ---------------- fused FF1+ReLU+FF2 (two 64-col hidden chunks) +residual+LN2
// smem 66.6 KB -> 3 blocks/SM.
__global__ __launch_bounds__(320, 3) void k_ffn(
    const float* __restrict__ w1, const float* __restrict__ b1,
    const float* __restrict__ w2, const float* __restrict__ b2,
    const float* __restrict__ g2, const float* __restrict__ be2,
    float* __restrict__ out)
{
    extern __shared__ __align__(16) float smx[];
    float* W1T = smx;             // 4096 [j][128]
    float* sb1 = smx + 4096;      // 128
    float* W2T = smx + 4224;      // 4096 [f][32]
    float* sb2 = smx + 8320;      // 32
    float* sg  = smx + 8352;      // 32
    float* sbe = smx + 8384;      // 32
    float* As  = smx + 8416;      // 80*33 = 2640
    float* Hs  = smx + 11056;     // 80*68 = 5440 (one 64-col chunk, stride 68)
    float* smu = smx + 16496;     // 80
    float* srs = smx + 16576;     // 80
    // total 16656 floats = 66624 B

    int tid = threadIdx.x;
    int s0 = blockIdx.x * 4;
    size_t base = (size_t)blockIdx.x * 80 * 32;

    for (int i = tid; i < 4096; i += 320) {
        { int f = i>>5, j = i&31;  W1T[j*128+f] = w1[i]; }
        { int d = i>>7, f = i&127; W2T[f*32+d]  = w2[i]; }
    }
    if (tid < 128) sb1[tid] = b1[tid];
    if (tid < 32) { sb2[tid]=b2[tid]; sg[tid]=g2[tid]; sbe[tid]=be2[tid]; }
    for (int i = tid; i < 2560; i += 320) As[(i>>5)*33+(i&31)] = g_tok2[base + i];
    __syncthreads();

    int rowg = tid>>3, colg = tid&7;   // rowg 0..39 (2 rows each), colg 0..7
    ull p0[2], p1[2];                  // FF2 accumulators, persist across chunks
    p0[0]=p0[1]=p1[0]=p1[1]=0ULL;

    #pragma unroll
    for (int cch = 0; cch < 2; cch++) {
        // ---- FF1 chunk: thread = 2 rows x 8 cols of this 64-wide chunk
        ull q0a[4], q1a[4];
        #pragma unroll
        for (int c = 0; c < 4; c++) { q0a[c]=0ULL; q1a[c]=0ULL; }
        #pragma unroll 8
        for (int j = 0; j < 32; j++) {
            const ulonglong2* wp2 = (const ulonglong2*)(W1T + j*128 + cch*64 + colg*8);
            ulonglong2 wA = wp2[0], wB = wp2[1];
            float a0 = As[(2*rowg)*33+j], a1 = As[(2*rowg+1)*33+j];
            ull a0p = pack2(a0,a0), a1p = pack2(a1,a1);
            ffma2(q0a[0], wA.x, a0p); ffma2(q0a[1], wA.y, a0p);
            ffma2(q0a[2], wB.x, a0p); ffma2(q0a[3], wB.y, a0p);
            ffma2(q1a[0], wA.x, a1p); ffma2(q1a[1], wA.y, a1p);
            ffma2(q1a[2], wB.x, a1p); ffma2(q1a[3], wB.y, a1p);
        }
        {
            float v0[8], v1[8];
            #pragma unroll
            for (int c = 0; c < 4; c++) { unpack2(q0a[c], v0[2*c], v0[2*c+1]); unpack2(q1a[c], v1[2*c], v1[2*c+1]); }
            #pragma unroll
            for (int c = 0; c < 8; c++) {
                v0[c] = fmaxf(v0[c] + sb1[cch*64 + colg*8 + c], 0.f);
                v1[c] = fmaxf(v1[c] + sb1[cch*64 + colg*8 + c], 0.f);
            }
            float4* d0 = (float4*)(Hs + (2*rowg)*68 + colg*8);
            float4* d1 = (float4*)(Hs + (2*rowg+1)*68 + colg*8);
            d0[0] = make_float4(v0[0],v0[1],v0[2],v0[3]);
            d0[1] = make_float4(v0[4],v0[5],v0[6],v0[7]);
            d1[0] = make_float4(v1[0],v1[1],v1[2],v1[3]);
            d1[1] = make_float4(v1[4],v1[5],v1[6],v1[7]);
        }
        __syncthreads();

        // ---- FF2 partial: accumulate this chunk's 64 f's
        #pragma unroll 8
        for (int f = 0; f < 64; f++) {
            const ulonglong2 wv2 = *(const ulonglong2*)(W2T + (cch*64+f)*32 + colg*4);
            float h0 = Hs[(2*rowg)*68+f], h1 = Hs[(2*rowg+1)*68+f];
            ull h0p = pack2(h0,h0), h1p = pack2(h1,h1);
            ffma2(p0[0], wv2.x, h0p); ffma2(p0[1], wv2.y, h0p);
            ffma2(p1[0], wv2.x, h1p); ffma2(p1[1], wv2.y, h1p);
        }
        __syncthreads();   // before next chunk overwrites Hs (or before Ps reuse)
    }

    float4 v0, v1;
    {
        float a0[4], a1[4];
        unpack2(p0[0], a0[0], a0[1]); unpack2(p0[1], a0[2], a0[3]);
        unpack2(p1[0], a1[0], a1[1]); unpack2(p1[1], a1[2], a1[3]);
        const float* r0 = As + (2*rowg)*33 + colg*4;
        const float* r1 = As + (2*rowg+1)*33 + colg*4;
        v0 = make_float4(a0[0]+sb2[colg*4+0]+r0[0], a0[1]+sb2[colg*4+1]+r0[1],
                         a0[2]+sb2[colg*4+2]+r0[2], a0[3]+sb2[colg*4+3]+r0[3]);
        v1 = make_float4(a1[0]+sb2[colg*4+0]+r1[0], a1[1]+sb2[colg*4+1]+r1[1],
                         a1[2]+sb2[colg*4+2]+r1[2], a1[3]+sb2[colg*4+3]+r1[3]);
    }
    float* Ps = Hs;    // reuse, stride 33 (2640 <= 5440)
    { float* d = Ps + (2*rowg)*33 + colg*4;   d[0]=v0.x; d[1]=v0.y; d[2]=v0.z; d[3]=v0.w; }
    { float* d = Ps + (2*rowg+1)*33 + colg*4; d[0]=v1.x; d[1]=v1.y; d[2]=v1.z; d[3]=v1.w; }
    __syncthreads();
    if (tid < 80) {
        const float* row = Ps + tid*33;
        float mu = 0.f;
        #pragma unroll
        for (int j = 0; j < 32; j++) mu += row[j];
        mu *= 0.03125f;
        float var = 0.f;
        #pragma unroll
        for (int j = 0; j < 32; j++) { float dd = row[j]-mu; var += dd*dd; }
        smu[tid] = mu; srs[tid] = rsqrtf(var*0.03125f + 1e-5f);
    }
    __syncthreads();
    for (int i = tid; i < 2560; i += 320) {
        int rr = i>>5, d = i&31;
        float o = (Ps[rr*33+d]-smu[rr])*srs[rr]*sg[d] + sbe[d];
        int sl = rr/20, t = rr - sl*20;
        int bt = s0 + sl;
        if (t < 19) out[7680 + (size_t)bt*608 + t*32 + d] = o;
        else        g_hm[(size_t)bt*32 + d] = o;
    }
}

// ---------------- LSTM x-gate precompute: block = (sd, 12 t's), 640 blocks
__global__ __launch_bounds__(384) void k_gates(
    const float* __restrict__ wihf, const float* __restrict__ bihf, const float* __restrict__ bhhf,
    const float* __restrict__ wihb, const float* __restrict__ bihb, const float* __restrict__ bhhb)
{
    __shared__ __align__(16) float swT[2048], sx[384], sb[64];
    int tid = threadIdx.x;
    int b = blockIdx.x;
    int sd = b / 10, q = b - sd*10;
    int s = sd >> 1, dir = sd & 1;
    const float* wih = dir ? wihb : wihf;
    const float* bih = dir ? bihb : bihf;
    const float* bhh = dir ? bhhb : bhhf;
    int t0 = q*12;

    for (int i = tid; i < 2048; i += 384) {
        int g = i >> 5, j = i & 31;
        swT[j*64 + g] = wih[i];
    }
    for (int i = tid; i < 384; i += 384) sx[i] = g_hm[(size_t)s*3840 + t0*32 + i];
    if (tid < 64) sb[tid] = bih[tid] + bhh[tid];
    __syncthreads();

    int g = tid & 63, tl = tid >> 6;   // tl 0..5, 2 t's each
    float b0 = sb[g];
    #pragma unroll
    for (int i = 0; i < 2; i++) {
        int t = tl*2 + i;
        const float* xr = sx + t*32;
        float a0=b0, a1=0.f, a2=0.f, a3=0.f;
        #pragma unroll
        for (int j = 0; j < 32; j += 4) {
            a0 = fmaf(xr[j+0], swT[(j+0)*64+g], a0);
            a1 = fmaf(xr[j+1], swT[(j+1)*64+g], a1);
            a2 = fmaf(xr[j+2], swT[(j+2)*64+g], a2);
            a3 = fmaf(xr[j+3], swT[(j+3)*64+g], a3);
        }
        g_xg[((size_t)sd*120 + t0 + t)*64 + g] = (a0+a1) + (a2+a3);
    }
}

// ---------------- LSTM recurrence: 1 warp per (seq, dir); no block barriers
__global__ __launch_bounds__(32) void k_lstm2(
    const float* __restrict__ whhf, const float* __restrict__ whhb)
{
    __shared__ __align__(16) float sxg[7680];
    __shared__ float sh[16];
    int l = threadIdx.x;
    int sd = blockIdx.x, s = sd >> 1, dir = sd & 1;
    const float* whh = dir ? whhb : whhf;
    float w0[16], w1[16];
    #pragma unroll
    for (int j = 0; j < 16; j++) { w0[j] = whh[l*16+j]; w1[j] = whh[(l+32)*16+j]; }
    {
        const float4* xg4 = (const float4*)(g_xg + (size_t)sd*7680);
        float4* s4 = (float4*)sxg;
        for (int i = l; i < 1920; i += 32) s4[i] = xg4[i];
    }
    if (l < 16) sh[l] = 0.f;
    __syncwarp();

    float c = 0.f;
    for (int t = 0; t < 120; t++) {
        int tt = dir ? (119-t) : t;
        const float* xr = sxg + tt*64;
        float g0 = xr[l], g1 = xr[l+32];
        float g0a=0.f, g0b=0.f, g1a=0.f, g1b=0.f;
        #pragma unroll
        for (int j = 0; j < 16; j += 2) {
            float h0 = sh[j], h1 = sh[j+1];
            g0a = fmaf(h0, w0[j],   g0a);
            g0b = fmaf(h1, w0[j+1], g0b);
            g1a = fmaf(h0, w1[j],   g1a);
            g1b = fmaf(h1, w1[j+1], g1b);
        }
        g0 += g0a + g0b;
        g1 += g1a + g1b;
        float fg = __shfl_sync(0xffffffffu, g0, l+16);
        float og = __shfl_sync(0xffffffffu, g1, l+16);
        if (l < 16) {
            c = fsig(fg)*c + fsig(g0)*ftanh(g1);
            float h = fsig(og)*ftanh(c);
            sh[l] = h;
            g_hcat[((size_t)s*120 + tt)*32 + dir*16 + l] = h;
        }
        __syncwarp();
    }
}

__global__ void k_lin(const float* __restrict__ lw, const float* __restrict__ lb,
                      float* __restrict__ out)
{
    int i = blockIdx.x*256 + threadIdx.x;
    if (i < 7680) {
        int bt = i>>1, o = i&1;
        const float* h = g_hcat + (size_t)bt*32;
        float acc = lb[o];
        #pragma unroll
        for (int k = 0; k < 32; k++) acc += h[k]*lw[o*32+k];
        out[i] = acc;
    }
}

extern "C" void kernel_launch(void* const* d_in, const int* in_sizes, int n_in,
                              void* d_out, int out_size)
{
    const float* x    = (const float*)d_in[0];
    const float* pos  = (const float*)d_in[1];
    const float* c1w  = (const float*)d_in[2];
    const float* c1b  = (const float*)d_in[3];
    const float* c2w  = (const float*)d_in[4];
    const float* c2b  = (const float*)d_in[5];
    const float* wq   = (const float*)d_in[6];
    const float* bq   = (const float*)d_in[7];
    const float* wk   = (const float*)d_in[8];
    const float* bk   = (const float*)d_in[9];
    const float* wv   = (const float*)d_in[10];
    const float* bv   = (const float*)d_in[11];
    const float* wo   = (const float*)d_in[12];
    const float* bo   = (const float*)d_in[13];
    const float* ln1g = (const float*)d_in[14];
    const float* ln1b = (const float*)d_in[15];
    const float* w1   = (const float*)d_in[16];
    const float* b1   = (const float*)d_in[17];
    const float* w2   = (const float*)d_in[18];
    const float* b2   = (const float*)d_in[19];
    const float* ln2g = (const float*)d_in[20];
    const float* ln2b = (const float*)d_in[21];
    const float* wihf = (const float*)d_in[22];
    const float* whhf = (const float*)d_in[23];
    const float* bihf = (const float*)d_in[24];
    const float* bhhf = (const float*)d_in[25];
    const float* wihb = (const float*)d_in[26];
    const float* whhb = (const float*)d_in[27];
    const float* bihb = (const float*)d_in[28];
    const float* bhhb = (const float*)d_in[29];
    const float* lw   = (const float*)d_in[30];
    const float* lb   = (const float*)d_in[31];
    float* out = (float*)d_out;

    cudaFuncSetAttribute(k_cnn,   cudaFuncAttributeMaxDynamicSharedMemorySize, 113*1024);
    cudaFuncSetAttribute(k_xform, cudaFuncAttributeMaxDynamicSharedMemorySize, 76*1024);
    cudaFuncSetAttribute(k_ffn,   cudaFuncAttributeMaxDynamicSharedMemorySize, 68*1024);

    k_cnn  <<<2280, 512, 110720>>>(x, c1w, c1b, c2w, c2b, pos);
    k_xform<<<960, 320, 74432>>>(wq, bq, wk, bk, wv, bv, wo, bo, ln1g, ln1b, pos);
    k_ffn  <<<960, 320, 66624>>>(w1, b1, w2, b2, ln2g, ln2b, out);
    k_gates<<<640, 384>>>(wihf, bihf, bhhf, wihb, bihb, bhhb);
    k_lstm2<<<64, 32>>>(whhf, whhb);
    k_lin  <<<30, 256>>>(lw, lb, out);
}

// round 15
// speedup vs baseline: 1.0442x; 1.0442x over previous
#include <cuda_runtime.h>
#include <math.h>

#define BT    3840
#define NROWS 76800

__device__ float g_tok [BT*19*32];
__device__ float g_tok2[NROWS*32];
__device__ float g_hm  [BT*32];
__device__ float g_hcat[BT*32];
__device__ float g_xg  [64*120*64];

__constant__ unsigned c_maskb[20] = {
    0x1Fu,0x73u,0x1DDu,0x33Du,0x23Bu,0x67Au,0xC76u,0x3984u,0x779Cu,0xE738u,
    0x1CF70u,0x18CC0u,0x33180u,0x2F380u,0x6E700u,0x5EE00u,0x59C00u,0x67000u,0x7C000u,0xFFFFFu
};

typedef unsigned long long ull;

__device__ __forceinline__ ull pack2(float lo, float hi){
    ull r;
    asm("mov.b64 %0, {%1, %2};" : "=l"(r) : "f"(lo), "f"(hi));
    return r;
}
__device__ __forceinline__ void unpack2(ull v, float& lo, float& hi){
    asm("mov.b64 {%0, %1}, %2;" : "=f"(lo), "=f"(hi) : "l"(v));
}
__device__ __forceinline__ void ffma2(ull& d, ull a, ull b){
    asm("fma.rn.f32x2 %0, %1, %2, %0;" : "+l"(d) : "l"(a), "l"(b));
}
__device__ __forceinline__ float fsig(float x){ return __fdividef(1.f, 1.f + __expf(-x)); }
__device__ __forceinline__ float ftanh(float x){
    float ax = fabsf(x);
    float e  = __expf(2.f*ax);
    float t  = 1.f - __fdividef(2.f, e + 1.f);
    return (x < 0.f) ? -t : t;
}

// ---------------- CNN: warp = sample pair; conv2 via packed f32x2 FMA
// 512 threads (16 warps, 32 samples) per block -> 2 blocks/SM = 32 warps/SM.
// Phase-1 x reads as LDS.128 over j-pairs (halves phase-1 wavefronts).
__global__ __launch_bounds__(512, 2) void k_cnn(
    const float* __restrict__ x, const float* __restrict__ c1w, const float* __restrict__ c1b,
    const float* __restrict__ c2w, const float* __restrict__ c2b, const float* __restrict__ pos)
{
    extern __shared__ __align__(16) float sm[];
    float* w2s = sm;              // 5120
    float* b2s = sm + 5120;       // 32
    float* uni = sm + 5152;       // union: sx[6400] then h1p[16*1408=22528]
    float* sx  = uni;
    float* h1p = uni;

    int tid = threadIdx.x, w = tid >> 5, oc = tid & 31;
    int n0 = blockIdx.x * 32;

    for (int i = tid; i < 5120; i += 512) {
        int o = i/160, r = i - o*160, ic = r/5, k = r - ic*5;
        w2s[(ic*5+k)*32 + o] = c2w[i];
    }
    if (tid < 32) b2s[tid] = c2b[tid];
    {
        const float4* xg = (const float4*)(x + (size_t)n0*200);
        float4* sx4 = (float4*)sx;
        for (int i = tid; i < 1600; i += 512) sx4[i] = xg[i];
    }
    __syncthreads();

    // ---- phase 1: conv1(s5)+relu+pool2, float4 j-pair reads
    float w1r[5];
    #pragma unroll
    for (int k = 0; k < 5; k++) w1r[k] = c1w[oc*5+k];
    float b1 = c1b[oc];
    float po[2][20];
    #pragma unroll
    for (int s = 0; s < 2; s++) {
        const float4* xw = (const float4*)(sx + (2*w+s)*200);
        #pragma unroll
        for (int m = 0; m < 10; m++) {
            float4 a  = xw[5*m+0];
            float4 b  = xw[5*m+1];
            float4 c4 = xw[5*m+2];
            float4 d4 = xw[5*m+3];
            float4 e  = xw[5*m+4];
            float o0 = b1 + a.x*w1r[0] + a.y*w1r[1] + a.z*w1r[2] + a.w*w1r[3] + b.x*w1r[4];
            float o1 = b1 + b.y*w1r[0] + b.z*w1r[1] + b.w*w1r[2] + c4.x*w1r[3] + c4.y*w1r[4];
            po[s][2*m] = fmaxf(fmaxf(o0,0.f), fmaxf(o1,0.f));
            float o2 = b1 + c4.z*w1r[0] + c4.w*w1r[1] + d4.x*w1r[2] + d4.y*w1r[3] + d4.z*w1r[4];
            float o3 = b1 + d4.w*w1r[0] + e.x*w1r[1] + e.y*w1r[2] + e.z*w1r[3] + e.w*w1r[4];
            po[s][2*m+1] = fmaxf(fmaxf(o2,0.f), fmaxf(o3,0.f));
        }
    }
    __syncthreads();   // all sx reads done; reuse as h1p

    float* hw = h1p + w*1408;
    #pragma unroll
    for (int t = 0; t < 20; t += 2) {
        float4 v = make_float4(po[0][t], po[1][t], po[0][t+1], po[1][t+1]);
        *(float4*)(hw + oc*44 + t*2) = v;
    }
    __syncwarp();

    ull acc[8];
    #pragma unroll
    for (int j = 0; j < 8; j++) acc[j] = 0ULL;
    #pragma unroll 2
    for (int ic = 0; ic < 32; ic++) {
        const ulonglong2* pv = (const ulonglong2*)(hw + ic*44);
        ull pr[20];
        #pragma unroll
        for (int q = 0; q < 10; q++) { ulonglong2 u = pv[q]; pr[2*q] = u.x; pr[2*q+1] = u.y; }
        ull wp[5];
        #pragma unroll
        for (int k = 0; k < 5; k++) { float wv_ = w2s[(ic*5+k)*32+oc]; wp[k] = pack2(wv_, wv_); }
        #pragma unroll
        for (int j = 0; j < 8; j++) {
            #pragma unroll
            for (int k = 0; k < 5; k++) ffma2(acc[j], pr[2*j+k], wp[k]);
        }
    }
    float aA[8], aB[8];
    #pragma unroll
    for (int j = 0; j < 8; j++) unpack2(acc[j], aA[j], aB[j]);
    float b2r = b2s[oc];
    #pragma unroll
    for (int s = 0; s < 2; s++) {
        const float* a = s ? aB : aA;
        float v = 0.f;
        #pragma unroll
        for (int u = 0; u < 4; u++)
            v += fmaxf(fmaxf(a[2*u]+b2r, 0.f), fmaxf(a[2*u+1]+b2r, 0.f));
        int n = n0 + 2*w + s, c = n % 19;
        g_tok[(size_t)n*32 + oc] = 0.25f*v + pos[c*32+oc];
    }
}

// ---------------- fused QKV + attention + proj + LN1 ; 4 samples/block, 320 thr
__global__ __launch_bounds__(320) void k_xform(
    const float* __restrict__ wq, const float* __restrict__ bq,
    const float* __restrict__ wk, const float* __restrict__ bk,
    const float* __restrict__ wv, const float* __restrict__ bv,
    const float* __restrict__ wo, const float* __restrict__ bo,
    const float* __restrict__ g1, const float* __restrict__ be1,
    const float* __restrict__ pos)
{
    extern __shared__ __align__(16) float smx[];
    float* WT   = smx;            // 3072
    float* sbq  = smx + 3072;     // 96
    float* WOT  = smx + 3168;     // 1024
    float* sbo  = smx + 4192;     // 32
    float* sg   = smx + 4224;     // 32
    float* sbe  = smx + 4256;     // 32
    float* As   = smx + 4288;     // 80*33
    float* QKV  = smx + 6928;     // 4*2160
    float* Os   = smx + 15568;    // 80*36
    float* smu  = smx + 18448;    // 80
    float* srs  = smx + 18528;    // 80

    int tid = threadIdx.x;
    int s0 = blockIdx.x * 4;

    for (int i = tid; i < 3072; i += 320) {
        int j = i/96, n = i%96;
        WT[i] = (n<32) ? wq[n*32+j] : (n<64) ? wk[(n-32)*32+j] : wv[(n-64)*32+j];
    }
    for (int i = tid; i < 96; i += 320) sbq[i] = (i<32)?bq[i]:(i<64)?bk[i-32]:bv[i-64];
    for (int i = tid; i < 1024; i += 320) { int d = i>>5, j = i&31; WOT[j*32+d] = wo[i]; }
    if (tid < 32) { sbo[tid]=bo[tid]; sg[tid]=g1[tid]; sbe[tid]=be1[tid]; }
    for (int i = tid; i < 640; i += 320) {
        int rr = i>>3, d4 = (i&7)*4;
        int sl = rr/20, t = rr - sl*20;
        const float4 v = (t < 19)
            ? *(const float4*)(g_tok + ((size_t)(s0+sl)*19 + t)*32 + d4)
            : *(const float4*)(pos + 19*32 + d4);
        float* d = As + rr*33 + d4;
        d[0]=v.x; d[1]=v.y; d[2]=v.z; d[3]=v.w;
    }
    __syncthreads();

    {
        int rowg = tid>>3, colg = tid&7;
        ull ap0[6], ap1[6];
        #pragma unroll
        for (int c = 0; c < 6; c++) { ap0[c]=0ULL; ap1[c]=0ULL; }
        #pragma unroll 8
        for (int j = 0; j < 32; j++) {
            float a0 = As[(2*rowg)*33+j], a1 = As[(2*rowg+1)*33+j];
            ull a0p = pack2(a0,a0), a1p = pack2(a1,a1);
            const ulonglong2* wp2 = (const ulonglong2*)(WT + j*96 + colg*12);
            ulonglong2 wA = wp2[0], wB = wp2[1], wC = wp2[2];
            ffma2(ap0[0], wA.x, a0p); ffma2(ap0[1], wA.y, a0p);
            ffma2(ap0[2], wB.x, a0p); ffma2(ap0[3], wB.y, a0p);
            ffma2(ap0[4], wC.x, a0p); ffma2(ap0[5], wC.y, a0p);
            ffma2(ap1[0], wA.x, a1p); ffma2(ap1[1], wA.y, a1p);
            ffma2(ap1[2], wB.x, a1p); ffma2(ap1[3], wB.y, a1p);
            ffma2(ap1[4], wC.x, a1p); ffma2(ap1[5], wC.y, a1p);
        }
        float acc0[12], acc1[12];
        #pragma unroll
        for (int c = 0; c < 6; c++) {
            unpack2(ap0[c], acc0[2*c], acc0[2*c+1]);
            unpack2(ap1[c], acc1[2*c], acc1[2*c+1]);
        }
        #pragma unroll
        for (int c = 0; c < 12; c++) {
            int n = colg*12 + c;
            int which = n>>5, d = n&31;
            float b = sbq[n];
            int rr0 = 2*rowg, rr1 = rr0+1;
            int sl0 = rr0/20, t0 = rr0 - sl0*20;
            int sl1 = rr1/20, t1 = rr1 - sl1*20;
            QKV[sl0*2160 + which*720 + t0*36 + d] = acc0[c] + b;
            QKV[sl1*2160 + which*720 + t1*36 + d] = acc1[c] + b;
        }
    }
    __syncthreads();

    #pragma unroll
    for (int pass = 0; pass < 2; pass++) {
        int hi = (tid >= 160);
        int sl = pass*2 + hi;
        int slot = tid - hi*160;
        int t = slot>>3, h = slot&7;
        const float* qs = QKV + sl*2160;
        const float* ks = qs + 720;
        const float* vs = qs + 1440;
        float4 q4 = *(const float4*)(qs + t*36 + h*4);
        unsigned mb = c_maskb[t];
        float sc[20], mx = -1e30f;
        #pragma unroll
        for (int kt = 0; kt < 20; kt++) {
            float4 k4 = *(const float4*)(ks + kt*36 + h*4);
            float s = 0.5f*(q4.x*k4.x+q4.y*k4.y+q4.z*k4.z+q4.w*k4.w);
            if (!((mb>>kt)&1u)) s = -1e9f;
            sc[kt] = s; mx = fmaxf(mx, s);
        }
        float sum = 0.f;
        #pragma unroll
        for (int kt = 0; kt < 20; kt++) { sc[kt] = __expf(sc[kt]-mx); sum += sc[kt]; }
        float inv = __fdividef(1.f, sum);
        float4 o = make_float4(0.f,0.f,0.f,0.f);
        #pragma unroll
        for (int kt = 0; kt < 20; kt++) {
            float a = sc[kt];
            float4 v4 = *(const float4*)(vs + kt*36 + h*4);
            o.x += a*v4.x; o.y += a*v4.y; o.z += a*v4.z; o.w += a*v4.w;
        }
        o.x *= inv; o.y *= inv; o.z *= inv; o.w *= inv;
        *(float4*)(Os + (sl*20 + t)*36 + h*4) = o;
    }
    __syncthreads();

    float* Ps = QKV;
    {
        int rowg = tid>>3, colg = tid&7;
        ull p0[2], p1[2];
        p0[0]=p0[1]=p1[0]=p1[1]=0ULL;
        #pragma unroll 8
        for (int j = 0; j < 32; j++) {
            const ulonglong2 wv2 = *(const ulonglong2*)(WOT + j*32 + colg*4);
            float x0 = Os[(2*rowg)*36+j], x1 = Os[(2*rowg+1)*36+j];
            ull x0p = pack2(x0,x0), x1p = pack2(x1,x1);
            ffma2(p0[0], wv2.x, x0p); ffma2(p0[1], wv2.y, x0p);
            ffma2(p1[0], wv2.x, x1p); ffma2(p1[1], wv2.y, x1p);
        }
        float a0[4], a1[4];
        unpack2(p0[0], a0[0], a0[1]); unpack2(p0[1], a0[2], a0[3]);
        unpack2(p1[0], a1[0], a1[1]); unpack2(p1[1], a1[2], a1[3]);
        #pragma unroll
        for (int i = 0; i < 2; i++) {
            int rr = 2*rowg + i;
            const float* res = As + rr*33 + colg*4;
            const float* ac = i ? a1 : a0;
            float* d = Ps + rr*33 + colg*4;
            d[0]=ac[0]+sbo[colg*4+0]+res[0];
            d[1]=ac[1]+sbo[colg*4+1]+res[1];
            d[2]=ac[2]+sbo[colg*4+2]+res[2];
            d[3]=ac[3]+sbo[colg*4+3]+res[3];
        }
    }
    __syncthreads();
    if (tid < 80) {
        const float* row = Ps + tid*33;
        float mu = 0.f;
        #pragma unroll
        for (int j = 0; j < 32; j++) mu += row[j];
        mu *= 0.03125f;
        float var = 0.f;
        #pragma unroll
        for (int j = 0; j < 32; j++) { float dd = row[j]-mu; var += dd*dd; }
        smu[tid] = mu; srs[tid] = rsqrtf(var*0.03125f + 1e-5f);
    }
    __syncthreads();
    size_t base = (size_t)blockIdx.x * 80 * 32;
    for (int i = tid; i < 2560; i += 320) {
        int rr = i>>5, d = i&31;
        g_tok2[base + i] = (Ps[rr*33+d]-smu[rr])*srs[rr]*sg[d] + sbe[d];
    }
}

// ---------------- fused FF1+ReLU+FF2+residual+LN2 + split write ; 4 samples/block
__global__ __launch_bounds__(320) void k_ffn(
    const float* __restrict__ w1, const float* __restrict__ b1,
    const float* __restrict__ w2, const float* __restrict__ b2,
    const float* __restrict__ g2, const float* __restrict__ be2,
    float* __restrict__ out)
{
    extern __shared__ __align__(16) float smx[];
    float* W1T = smx;             // 4096
    float* sb1 = smx + 4096;      // 128
    float* W2T = smx + 4224;      // 4096
    float* sb2 = smx + 8320;      // 32
    float* sg  = smx + 8352;      // 32
    float* sbe = smx + 8384;      // 32
    float* As  = smx + 8416;      // 80*33
    float* Hs  = smx + 11056;     // 80*132
    float* smu = smx + 21616;     // 80
    float* srs = smx + 21696;     // 80

    int tid = threadIdx.x;
    int s0 = blockIdx.x * 4;
    size_t base = (size_t)blockIdx.x * 80 * 32;

    for (int i = tid; i < 4096; i += 320) {
        { int f = i>>5, j = i&31;  W1T[j*128+f] = w1[i]; }
        { int d = i>>7, f = i&127; W2T[f*32+d]  = w2[i]; }
    }
    if (tid < 128) sb1[tid] = b1[tid];
    if (tid < 32) { sb2[tid]=b2[tid]; sg[tid]=g2[tid]; sbe[tid]=be2[tid]; }
    for (int i = tid; i < 2560; i += 320) As[(i>>5)*33+(i&31)] = g_tok2[base + i];
    __syncthreads();

    {
        int rowg = tid>>4, colg = tid&15;
        ull accp[4][4];
        #pragma unroll
        for (int i = 0; i < 4; i++)
            #pragma unroll
            for (int c = 0; c < 4; c++) accp[i][c] = 0ULL;
        #pragma unroll 4
        for (int j = 0; j < 32; j++) {
            const ulonglong2* wp2 = (const ulonglong2*)(W1T + j*128 + colg*8);
            ulonglong2 wA = wp2[0], wB = wp2[1];
            #pragma unroll
            for (int i = 0; i < 4; i++) {
                float a = As[(4*rowg+i)*33+j];
                ull ap = pack2(a,a);
                ffma2(accp[i][0], wA.x, ap); ffma2(accp[i][1], wA.y, ap);
                ffma2(accp[i][2], wB.x, ap); ffma2(accp[i][3], wB.y, ap);
            }
        }
        #pragma unroll
        for (int i = 0; i < 4; i++) {
            float v[8];
            #pragma unroll
            for (int c = 0; c < 4; c++) unpack2(accp[i][c], v[2*c], v[2*c+1]);
            #pragma unroll
            for (int c = 0; c < 8; c++)
                Hs[(4*rowg+i)*132 + colg*8+c] = fmaxf(v[c]+sb1[colg*8+c], 0.f);
        }
    }
    __syncthreads();

    int rowg = tid>>3, colg = tid&7;
    float4 v0, v1;
    {
        ull p0[2], p1[2];
        p0[0]=p0[1]=p1[0]=p1[1]=0ULL;
        #pragma unroll 8
        for (int f = 0; f < 128; f++) {
            const ulonglong2 wv2 = *(const ulonglong2*)(W2T + f*32 + colg*4);
            float h0 = Hs[(2*rowg)*132+f], h1 = Hs[(2*rowg+1)*132+f];
            ull h0p = pack2(h0,h0), h1p = pack2(h1,h1);
            ffma2(p0[0], wv2.x, h0p); ffma2(p0[1], wv2.y, h0p);
            ffma2(p1[0], wv2.x, h1p); ffma2(p1[1], wv2.y, h1p);
        }
        float a0[4], a1[4];
        unpack2(p0[0], a0[0], a0[1]); unpack2(p0[1], a0[2], a0[3]);
        unpack2(p1[0], a1[0], a1[1]); unpack2(p1[1], a1[2], a1[3]);
        const float* r0 = As + (2*rowg)*33 + colg*4;
        const float* r1 = As + (2*rowg+1)*33 + colg*4;
        v0 = make_float4(a0[0]+sb2[colg*4+0]+r0[0], a0[1]+sb2[colg*4+1]+r0[1],
                         a0[2]+sb2[colg*4+2]+r0[2], a0[3]+sb2[colg*4+3]+r0[3]);
        v1 = make_float4(a1[0]+sb2[colg*4+0]+r1[0], a1[1]+sb2[colg*4+1]+r1[1],
                         a1[2]+sb2[colg*4+2]+r1[2], a1[3]+sb2[colg*4+3]+r1[3]);
    }
    __syncthreads();
    float* Ps = Hs;
    { float* d = Ps + (2*rowg)*33 + colg*4;   d[0]=v0.x; d[1]=v0.y; d[2]=v0.z; d[3]=v0.w; }
    { float* d = Ps + (2*rowg+1)*33 + colg*4; d[0]=v1.x; d[1]=v1.y; d[2]=v1.z; d[3]=v1.w; }
    __syncthreads();
    if (tid < 80) {
        const float* row = Ps + tid*33;
        float mu = 0.f;
        #pragma unroll
        for (int j = 0; j < 32; j++) mu += row[j];
        mu *= 0.03125f;
        float var = 0.f;
        #pragma unroll
        for (int j = 0; j < 32; j++) { float dd = row[j]-mu; var += dd*dd; }
        smu[tid] = mu; srs[tid] = rsqrtf(var*0.03125f + 1e-5f);
    }
    __syncthreads();
    for (int i = tid; i < 2560; i += 320) {
        int rr = i>>5, d = i&31;
        float o = (Ps[rr*33+d]-smu[rr])*srs[rr]*sg[d] + sbe[d];
        int sl = rr/20, t = rr - sl*20;
        int bt = s0 + sl;
        if (t < 19) out[7680 + (size_t)bt*608 + t*32 + d] = o;
        else        g_hm[(size_t)bt*32 + d] = o;
    }
}

// ---------------- LSTM x-gate precompute (parallel): block = (sd, 24 t's), 384 thr
__global__ __launch_bounds__(384) void k_gates(
    const float* __restrict__ wihf, const float* __restrict__ bihf, const float* __restrict__ bhhf,
    const float* __restrict__ wihb, const float* __restrict__ bihb, const float* __restrict__ bhhb)
{
    __shared__ __align__(16) float swT[2048], sx[768], sb[64];
    int tid = threadIdx.x;
    int b = blockIdx.x;
    int sd = b / 5, q = b - sd*5;
    int s = sd >> 1, dir = sd & 1;
    const float* wih = dir ? wihb : wihf;
    const float* bih = dir ? bihb : bihf;
    const float* bhh = dir ? bhhb : bhhf;
    int t0 = q*24;

    for (int i = tid; i < 2048; i += 384) {
        int g = i >> 5, j = i & 31;
        swT[j*64 + g] = wih[i];
    }
    for (int i = tid; i < 768; i += 384) sx[i] = g_hm[(size_t)s*3840 + t0*32 + i];
    if (tid < 64) sb[tid] = bih[tid] + bhh[tid];
    __syncthreads();

    int g = tid & 63, tl = tid >> 6;
    float b0 = sb[g];
    #pragma unroll
    for (int i = 0; i < 4; i++) {
        int t = tl*4 + i;
        const float* xr = sx + t*32;
        float a0=b0, a1=0.f, a2=0.f, a3=0.f;
        #pragma unroll
        for (int j = 0; j < 32; j += 4) {
            a0 = fmaf(xr[j+0], swT[(j+0)*64+g], a0);
            a1 = fmaf(xr[j+1], swT[(j+1)*64+g], a1);
            a2 = fmaf(xr[j+2], swT[(j+2)*64+g], a2);
            a3 = fmaf(xr[j+3], swT[(j+3)*64+g], a3);
        }
        g_xg[((size_t)sd*120 + t0 + t)*64 + g] = (a0+a1) + (a2+a3);
    }
}

// ---------------- LSTM recurrence: 1 warp per (seq, dir); no block barriers
__global__ __launch_bounds__(32) void k_lstm2(
    const float* __restrict__ whhf, const float* __restrict__ whhb)
{
    __shared__ __align__(16) float sxg[7680];
    __shared__ float sh[16];
    int l = threadIdx.x;
    int sd = blockIdx.x, s = sd >> 1, dir = sd & 1;
    const float* whh = dir ? whhb : whhf;
    float w0[16], w1[16];
    #pragma unroll
    for (int j = 0; j < 16; j++) { w0[j] = whh[l*16+j]; w1[j] = whh[(l+32)*16+j]; }
    {
        const float4* xg4 = (const float4*)(g_xg + (size_t)sd*7680);
        float4* s4 = (float4*)sxg;
        for (int i = l; i < 1920; i += 32) s4[i] = xg4[i];
    }
    if (l < 16) sh[l] = 0.f;
    __syncwarp();

    float c = 0.f;
    for (int t = 0; t < 120; t++) {
        int tt = dir ? (119-t) : t;
        const float* xr = sxg + tt*64;
        float g0 = xr[l], g1 = xr[l+32];
        float g0a=0.f, g0b=0.f, g1a=0.f, g1b=0.f;
        #pragma unroll
        for (int j = 0; j < 16; j += 2) {
            float h0 = sh[j], h1 = sh[j+1];
            g0a = fmaf(h0, w0[j],   g0a);
            g0b = fmaf(h1, w0[j+1], g0b);
            g1a = fmaf(h0, w1[j],   g1a);
            g1b = fmaf(h1, w1[j+1], g1b);
        }
        g0 += g0a + g0b;
        g1 += g1a + g1b;
        float fg = __shfl_sync(0xffffffffu, g0, l+16);
        float og = __shfl_sync(0xffffffffu, g1, l+16);
        if (l < 16) {
            c = fsig(fg)*c + fsig(g0)*ftanh(g1);
            float h = fsig(og)*ftanh(c);
            sh[l] = h;
            g_hcat[((size_t)s*120 + tt)*32 + dir*16 + l] = h;
        }
        __syncwarp();
    }
}

__global__ void k_lin(const float* __restrict__ lw, const float* __restrict__ lb,
                      float* __restrict__ out)
{
    int i = blockIdx.x*256 + threadIdx.x;
    if (i < 7680) {
        int bt = i>>1, o = i&1;
        const float* h = g_hcat + (size_t)bt*32;
        float acc = lb[o];
        #pragma unroll
        for (int k = 0; k < 32; k++) acc += h[k]*lw[o*32+k];
        out[i] = acc;
    }
}

extern "C" void kernel_launch(void* const* d_in, const int* in_sizes, int n_in,
                              void* d_out, int out_size)
{
    const float* x    = (const float*)d_in[0];
    const float* pos  = (const float*)d_in[1];
    const float* c1w  = (const float*)d_in[2];
    const float* c1b  = (const float*)d_in[3];
    const float* c2w  = (const float*)d_in[4];
    const float* c2b  = (const float*)d_in[5];
    const float* wq   = (const float*)d_in[6];
    const float* bq   = (const float*)d_in[7];
    const float* wk   = (const float*)d_in[8];
    const float* bk   = (const float*)d_in[9];
    const float* wv   = (const float*)d_in[10];
    const float* bv   = (const float*)d_in[11];
    const float* wo   = (const float*)d_in[12];
    const float* bo   = (const float*)d_in[13];
    const float* ln1g = (const float*)d_in[14];
    const float* ln1b = (const float*)d_in[15];
    const float* w1   = (const float*)d_in[16];
    const float* b1   = (const float*)d_in[17];
    const float* w2   = (const float*)d_in[18];
    const float* b2   = (const float*)d_in[19];
    const float* ln2g = (const float*)d_in[20];
    const float* ln2b = (const float*)d_in[21];
    const float* wihf = (const float*)d_in[22];
    const float* whhf = (const float*)d_in[23];
    const float* bihf = (const float*)d_in[24];
    const float* bhhf = (const float*)d_in[25];
    const float* wihb = (const float*)d_in[26];
    const float* whhb = (const float*)d_in[27];
    const float* bihb = (const float*)d_in[28];
    const float* bhhb = (const float*)d_in[29];
    const float* lw   = (const float*)d_in[30];
    const float* lb   = (const float*)d_in[31];
    float* out = (float*)d_out;

    cudaFuncSetAttribute(k_cnn,   cudaFuncAttributeMaxDynamicSharedMemorySize, 113*1024);
    cudaFuncSetAttribute(k_xform, cudaFuncAttributeMaxDynamicSharedMemorySize, 80*1024);
    cudaFuncSetAttribute(k_ffn,   cudaFuncAttributeMaxDynamicSharedMemorySize, 96*1024);

    k_cnn  <<<2280, 512, 110720>>>(x, c1w, c1b, c2w, c2b, pos);
    k_xform<<<960, 320, 74432>>>(wq, bq, wk, bk, wv, bv, wo, bo, ln1g, ln1b, pos);
    k_ffn  <<<960, 320, 87104>>>(w1, b1, w2, b2, ln2g, ln2b, out);
    k_gates<<<320, 384>>>(wihf, bihf, bhhf, wihb, bihb, bhhb);
    k_lstm2<<<64, 32>>>(whhf, whhb);
    k_lin  <<<30, 256>>>(lw, lb, out);
}